// round 6
// baseline (speedup 1.0000x reference)
#include <cuda_runtime.h>
#include <cstdint>

#define NN 50000
#define EE 640000
#define FIN 768
#define HD 128
#define TOT (EE + NN)
#define NEG_SLOPE 0.2f

// ---------------- scratch (device globals; no allocation allowed) ----------------
__device__ float g_xl[NN * HD];
__device__ float g_xr[NN * HD];
__device__ float g_hA[NN * HD];
__device__ float g_hB[NN * HD];
__device__ int   g_counts[NN];
__device__ int   g_local[NN];
__device__ int   g_rowptr[NN + 1];
__device__ int   g_cursor[NN];
__device__ int   g_srcarr[TOT];
__device__ int   g_blocksums[64];
__device__ float g_pool[HD];

// buffer selector: 0=xl 1=xr 2=hA 3=hB
__device__ __forceinline__ float* buf(int i) {
    return i == 0 ? g_xl : i == 1 ? g_xr : i == 2 ? g_hA : g_hB;
}

// ---------------- CSR build ----------------
__global__ void k_init() {
    int i = blockIdx.x * blockDim.x + threadIdx.x;
    if (i < NN) g_counts[i] = 1;          // self loop
    if (i < HD) g_pool[i] = 0.f;
}

__global__ void k_hist(const int* __restrict__ ei) {
    int e = blockIdx.x * blockDim.x + threadIdx.x;
    if (e < EE) {
        int d = ei[EE + e];
        atomicAdd(&g_counts[d], 1);
    }
}

__global__ void k_scan_block() {
    __shared__ int sm[1024];
    int i = blockIdx.x * 1024 + threadIdx.x;
    int v = (i < NN) ? g_counts[i] : 0;
    sm[threadIdx.x] = v;
    __syncthreads();
    for (int off = 1; off < 1024; off <<= 1) {
        int t = (threadIdx.x >= off) ? sm[threadIdx.x - off] : 0;
        __syncthreads();
        sm[threadIdx.x] += t;
        __syncthreads();
    }
    if (i < NN) g_local[i] = sm[threadIdx.x] - v;   // exclusive
    if (threadIdx.x == 1023) g_blocksums[blockIdx.x] = sm[1023];
}

__global__ void k_scan_top(int nb) {
    __shared__ int sm[64];
    int t = threadIdx.x;
    int v = (t < nb) ? g_blocksums[t] : 0;
    sm[t] = v;
    __syncthreads();
    for (int off = 1; off < 64; off <<= 1) {
        int u = (t >= off) ? sm[t - off] : 0;
        __syncthreads();
        sm[t] += u;
        __syncthreads();
    }
    if (t < nb) g_blocksums[t] = sm[t] - v;         // exclusive
}

__global__ void k_finalize_csr() {
    int i = blockIdx.x * blockDim.x + threadIdx.x;
    if (i < NN) {
        int off = g_local[i] + g_blocksums[i >> 10];
        g_rowptr[i] = off;
        g_cursor[i] = off + 1;      // slot 0 reserved for self loop
        g_srcarr[off] = i;          // self loop
    }
    if (i == 0) g_rowptr[NN] = TOT;
}

__global__ void k_scatter(const int* __restrict__ ei) {
    int e = blockIdx.x * blockDim.x + threadIdx.x;
    if (e < EE) {
        int s = ei[e];
        int d = ei[EE + e];
        int pos = atomicAdd(&g_cursor[d], 1);
        g_srcarr[pos] = s;
    }
}

// ---------------- tf32 tensor-core dual GEMM ----------------
// Computes BOTH  xl = A @ B1  and  xr = A @ B2  in one launch.
// Halves INTERLEAVED: blockIdx even -> B1/xl, odd -> B2/xr; adjacent blocks
// share the same A slab -> co-resident -> L2 reuse of A.
__device__ __forceinline__ uint32_t to_tf32(float x) {
    uint32_t r;
    asm("cvt.rna.tf32.f32 %0, %1;" : "=r"(r) : "f"(x));
    return r;
}

#define AS_STRIDE 20
#define BS_STRIDE 136

__global__ void __launch_bounds__(256, 2)
k_mma_dual(const float* __restrict__ Aext, int Asel,
           const float* __restrict__ B1, const float* __restrict__ B2,
           int M, int K) {
    const float* __restrict__ A = (Asel < 0) ? Aext : buf(Asel);

    const int half = blockIdx.x & 1;
    const int blk  = blockIdx.x >> 1;
    const float* __restrict__ B = half ? B2 : B1;
    float* __restrict__ C = half ? g_xr : g_xl;

    __shared__ uint32_t As[2][128 * AS_STRIDE];
    __shared__ uint32_t Bs[2][16 * BS_STRIDE];

    const int tid  = threadIdx.x;
    const int wid  = tid >> 5;
    const int lane = tid & 31;
    const int g = lane >> 2;
    const int t = lane & 3;
    const int warpM = wid & 1;   // 2 warps in M (64 rows each)
    const int warpN = wid >> 1;  // 4 warps in N (32 cols each)
    const int row0 = blk * 128;

    float acc[4][4][4];
    #pragma unroll
    for (int i = 0; i < 4; i++)
        #pragma unroll
        for (int j = 0; j < 4; j++)
            #pragma unroll
            for (int k = 0; k < 4; k++) acc[i][j][k] = 0.f;

    float4 ra[2], rb[2];

    // ---- load tile 0 ----
    #pragma unroll
    for (int i = 0; i < 2; i++) {
        int idx = tid + i * 256;
        int r  = idx >> 2, kq = idx & 3;
        int gr = row0 + r;
        ra[i] = (gr < M) ? *reinterpret_cast<const float4*>(&A[(size_t)gr * K + kq * 4])
                         : make_float4(0.f, 0.f, 0.f, 0.f);
        int kk = idx >> 5, nq = idx & 31;
        rb[i] = *reinterpret_cast<const float4*>(&B[(size_t)kk * 128 + nq * 4]);
    }
    #pragma unroll
    for (int i = 0; i < 2; i++) {
        int idx = tid + i * 256;
        int r  = idx >> 2, kq = idx & 3;
        uint32_t* da = &As[0][r * AS_STRIDE + kq * 4];
        da[0] = to_tf32(ra[i].x); da[1] = to_tf32(ra[i].y);
        da[2] = to_tf32(ra[i].z); da[3] = to_tf32(ra[i].w);
        int kk = idx >> 5, nq = idx & 31;
        uint32_t* db = &Bs[0][kk * BS_STRIDE + nq * 4];
        db[0] = to_tf32(rb[i].x); db[1] = to_tf32(rb[i].y);
        db[2] = to_tf32(rb[i].z); db[3] = to_tf32(rb[i].w);
    }
    __syncthreads();

    const int niter = K >> 4;
    int cur = 0;
    for (int it = 0; it < niter; it++) {
        const bool has_next = (it + 1 < niter);
        const int k0n = (it + 1) << 4;
        if (has_next) {
            #pragma unroll
            for (int i = 0; i < 2; i++) {
                int idx = tid + i * 256;
                int r  = idx >> 2, kq = idx & 3;
                int gr = row0 + r;
                ra[i] = (gr < M) ? *reinterpret_cast<const float4*>(&A[(size_t)gr * K + k0n + kq * 4])
                                 : make_float4(0.f, 0.f, 0.f, 0.f);
                int kk = idx >> 5, nq = idx & 31;
                rb[i] = *reinterpret_cast<const float4*>(&B[(size_t)(k0n + kk) * 128 + nq * 4]);
            }
        }

        const uint32_t* __restrict__ Ab = As[cur];
        const uint32_t* __restrict__ Bb = Bs[cur];
        #pragma unroll
        for (int ks = 0; ks < 16; ks += 8) {
            uint32_t afr[4][4];
            #pragma unroll
            for (int mt = 0; mt < 4; mt++) {
                int rowb = warpM * 64 + mt * 16;
                afr[mt][0] = Ab[(rowb + g)     * AS_STRIDE + ks + t];
                afr[mt][1] = Ab[(rowb + g + 8) * AS_STRIDE + ks + t];
                afr[mt][2] = Ab[(rowb + g)     * AS_STRIDE + ks + t + 4];
                afr[mt][3] = Ab[(rowb + g + 8) * AS_STRIDE + ks + t + 4];
            }
            uint32_t bfr[4][2];
            #pragma unroll
            for (int nt = 0; nt < 4; nt++) {
                int nbase = warpN * 32 + nt * 8;
                bfr[nt][0] = Bb[(ks + t)     * BS_STRIDE + nbase + g];
                bfr[nt][1] = Bb[(ks + t + 4) * BS_STRIDE + nbase + g];
            }
            #pragma unroll
            for (int mt = 0; mt < 4; mt++)
                #pragma unroll
                for (int nt = 0; nt < 4; nt++) {
                    asm volatile(
                        "mma.sync.aligned.m16n8k8.row.col.f32.tf32.tf32.f32 "
                        "{%0,%1,%2,%3}, {%4,%5,%6,%7}, {%8,%9}, {%0,%1,%2,%3};"
                        : "+f"(acc[mt][nt][0]), "+f"(acc[mt][nt][1]),
                          "+f"(acc[mt][nt][2]), "+f"(acc[mt][nt][3])
                        : "r"(afr[mt][0]), "r"(afr[mt][1]), "r"(afr[mt][2]), "r"(afr[mt][3]),
                          "r"(bfr[nt][0]), "r"(bfr[nt][1]));
                }
        }

        if (has_next) {
            int nxt = cur ^ 1;
            #pragma unroll
            for (int i = 0; i < 2; i++) {
                int idx = tid + i * 256;
                int r  = idx >> 2, kq = idx & 3;
                uint32_t* da = &As[nxt][r * AS_STRIDE + kq * 4];
                da[0] = to_tf32(ra[i].x); da[1] = to_tf32(ra[i].y);
                da[2] = to_tf32(ra[i].z); da[3] = to_tf32(ra[i].w);
                int kk = idx >> 5, nq = idx & 31;
                uint32_t* db = &Bs[nxt][kk * BS_STRIDE + nq * 4];
                db[0] = to_tf32(rb[i].x); db[1] = to_tf32(rb[i].y);
                db[2] = to_tf32(rb[i].z); db[3] = to_tf32(rb[i].w);
            }
        }
        __syncthreads();
        cur ^= 1;
    }

    // epilogue
    #pragma unroll
    for (int mt = 0; mt < 4; mt++) {
        int r0 = row0 + warpM * 64 + mt * 16 + g;
        #pragma unroll
        for (int nt = 0; nt < 4; nt++) {
            int c = warpN * 32 + nt * 8 + t * 2;
            if (r0 < M)
                *reinterpret_cast<float2*>(&C[(size_t)r0 * 128 + c]) =
                    make_float2(acc[mt][nt][0], acc[mt][nt][1]);
            if (r0 + 8 < M)
                *reinterpret_cast<float2*>(&C[(size_t)(r0 + 8) * 128 + c]) =
                    make_float2(acc[mt][nt][2], acc[mt][nt][3]);
        }
    }
}

// ---------------- GATv2 aggregation: one warp per node, online softmax ----------------
__device__ __forceinline__ float lrelu(float v) { return v > 0.f ? v : NEG_SLOPE * v; }

__global__ void k_aggregate(const float* __restrict__ att, const float* __restrict__ bias,
                            int outsel, int do_relu) {
    int warp = (blockIdx.x * blockDim.x + threadIdx.x) >> 5;
    if (warp >= NN) return;
    int lane = threadIdx.x & 31;
    const float* __restrict__ xl = g_xl;
    const float* __restrict__ xr = g_xr;
    float* __restrict__ out = buf(outsel);

    const float4 xrv  = *reinterpret_cast<const float4*>(&xr[(size_t)warp * HD + lane * 4]);
    const float4 attv = *reinterpret_cast<const float4*>(&att[lane * 4]);

    float m = -1e30f, s = 0.f;
    float4 acc = make_float4(0.f, 0.f, 0.f, 0.f);

    const int beg = g_rowptr[warp];
    const int end = g_rowptr[warp + 1];

    // 2-deep software pipeline: two xl-row gathers in flight
    float4 r0 = *reinterpret_cast<const float4*>(
        &xl[(size_t)g_srcarr[beg] * HD + lane * 4]);
    float4 r1 = r0;
    if (beg + 1 < end)
        r1 = *reinterpret_cast<const float4*>(
            &xl[(size_t)g_srcarr[beg + 1] * HD + lane * 4]);

    for (int e = beg; e < end; e++) {
        float4 xlv = r0;
        r0 = r1;
        if (e + 2 < end) {
            int s2 = g_srcarr[e + 2];
            r1 = *reinterpret_cast<const float4*>(&xl[(size_t)s2 * HD + lane * 4]);
        }
        float p = lrelu(xlv.x + xrv.x) * attv.x
                + lrelu(xlv.y + xrv.y) * attv.y
                + lrelu(xlv.z + xrv.z) * attv.z
                + lrelu(xlv.w + xrv.w) * attv.w;
        p += __shfl_xor_sync(0xffffffffu, p, 1);
        p += __shfl_xor_sync(0xffffffffu, p, 2);
        p += __shfl_xor_sync(0xffffffffu, p, 4);
        float eh = p;
        if (eh > m) {
            float sc = __expf(m - eh);
            s *= sc;
            acc.x *= sc; acc.y *= sc; acc.z *= sc; acc.w *= sc;
            m = eh;
        }
        float w = __expf(eh - m);
        s += w;
        acc.x += w * xlv.x; acc.y += w * xlv.y;
        acc.z += w * xlv.z; acc.w += w * xlv.w;
    }
    float inv = 1.f / (s + 1e-16f);
    const float4 bv = *reinterpret_cast<const float4*>(&bias[lane * 4]);
    float4 o;
    o.x = acc.x * inv + bv.x;
    o.y = acc.y * inv + bv.y;
    o.z = acc.z * inv + bv.z;
    o.w = acc.w * inv + bv.w;
    if (do_relu) {
        o.x = fmaxf(o.x, 0.f); o.y = fmaxf(o.y, 0.f);
        o.z = fmaxf(o.z, 0.f); o.w = fmaxf(o.w, 0.f);
    }
    *reinterpret_cast<float4*>(&out[(size_t)warp * HD + lane * 4]) = o;
}

// ---------------- pooling + classifier ----------------
__global__ void k_pool(int hsel) {
    const float* __restrict__ h = buf(hsel);
    int col = threadIdx.x;   // blockDim = 128
    float acc = 0.f;
    for (int r = blockIdx.x; r < NN; r += gridDim.x)
        acc += h[(size_t)r * HD + col];
    atomicAdd(&g_pool[col], acc);
}

__global__ void k_classify(const float* __restrict__ W, const float* __restrict__ b,
                           float* __restrict__ out) {
    int j = threadIdx.x;
    if (j < 2) {
        float s = 0.f;
        const float invn = 1.f / (float)NN;
        for (int k = 0; k < HD; k++)
            s += g_pool[k] * invn * W[k * 2 + j];
        out[j] = s + b[j];
    }
}

// ---------------- launch ----------------
extern "C" void kernel_launch(void* const* d_in, const int* in_sizes, int n_in,
                              void* d_out, int out_size) {
    const float* x  = (const float*)d_in[0];
    const int*   ei = (const int*)d_in[1];   // delivered as int32 (JAX x64 disabled)
    const float* Wl[4]  = {(const float*)d_in[2],  (const float*)d_in[6],
                           (const float*)d_in[10], (const float*)d_in[14]};
    const float* Wr[4]  = {(const float*)d_in[3],  (const float*)d_in[7],
                           (const float*)d_in[11], (const float*)d_in[15]};
    const float* att[4] = {(const float*)d_in[4],  (const float*)d_in[8],
                           (const float*)d_in[12], (const float*)d_in[16]};
    const float* bia[4] = {(const float*)d_in[5],  (const float*)d_in[9],
                           (const float*)d_in[13], (const float*)d_in[17]};
    const float* clfW = (const float*)d_in[18];
    const float* clfb = (const float*)d_in[19];
    float* out = (float*)d_out;

    const int TB = 256;
    const int gN  = (NN + TB - 1) / TB;
    const int gE  = (EE + TB - 1) / TB;
    const int gSc = (NN + 1023) / 1024;            // 49
    const int gGm = 2 * ((NN + 127) / 128);        // 782 (dual, interleaved)
    const int gAg = (NN * 32 + TB - 1) / TB;       // warp per node

    // CSR by dst (rebuilt every call: deterministic work)
    k_init<<<gN, TB>>>();
    k_hist<<<gE, TB>>>(ei);
    k_scan_block<<<gSc, 1024>>>();
    k_scan_top<<<1, 64>>>(gSc);
    k_finalize_csr<<<gN, TB>>>();
    k_scatter<<<gE, TB>>>(ei);

    // layer 1 (K=768): A = external x
    k_mma_dual<<<gGm, TB>>>(x, -1, Wl[0], Wr[0], NN, FIN);
    k_aggregate<<<gAg, TB>>>(att[0], bia[0], 2, 1);
    // layer 2: A = hA(2)
    k_mma_dual<<<gGm, TB>>>(nullptr, 2, Wl[1], Wr[1], NN, HD);
    k_aggregate<<<gAg, TB>>>(att[1], bia[1], 3, 1);
    // layer 3: A = hB(3)
    k_mma_dual<<<gGm, TB>>>(nullptr, 3, Wl[2], Wr[2], NN, HD);
    k_aggregate<<<gAg, TB>>>(att[2], bia[2], 2, 1);
    // layer 4 (no relu): A = hA(2)
    k_mma_dual<<<gGm, TB>>>(nullptr, 2, Wl[3], Wr[3], NN, HD);
    k_aggregate<<<gAg, TB>>>(att[3], bia[3], 3, 0);

    // mean-pool + classifier
    k_pool<<<512, 128>>>(3);
    k_classify<<<1, 32>>>(clfW, clfb, out);
}

// round 8
// speedup vs baseline: 1.0370x; 1.0370x over previous
#include <cuda_runtime.h>
#include <cstdint>

#define NN 50000
#define EE 640000
#define FIN 768
#define HD 128
#define TOT (EE + NN)
#define NEG_SLOPE 0.2f

// ---------------- scratch (device globals; no allocation allowed) ----------------
__device__ float g_xl[NN * HD];
__device__ float g_xr[NN * HD];
__device__ float g_hA[NN * HD];
__device__ float g_hB[NN * HD];
__device__ int   g_counts[NN];
__device__ int   g_local[NN];
__device__ int   g_rowptr[NN + 1];
__device__ int   g_cursor[NN];
__device__ int   g_srcarr[TOT];
__device__ int   g_blocksums[64];
__device__ float g_pool[HD];

// buffer selector: 0=xl 1=xr 2=hA 3=hB
__device__ __forceinline__ float* buf(int i) {
    return i == 0 ? g_xl : i == 1 ? g_xr : i == 2 ? g_hA : g_hB;
}

// ---------------- CSR build ----------------
__global__ void k_init() {
    int i = blockIdx.x * blockDim.x + threadIdx.x;
    if (i < NN) g_counts[i] = 1;          // self loop
    if (i < HD) g_pool[i] = 0.f;
}

__global__ void k_hist(const int* __restrict__ ei) {
    int e = blockIdx.x * blockDim.x + threadIdx.x;
    if (e < EE) {
        int d = ei[EE + e];
        atomicAdd(&g_counts[d], 1);
    }
}

__global__ void k_scan_block() {
    __shared__ int sm[1024];
    int i = blockIdx.x * 1024 + threadIdx.x;
    int v = (i < NN) ? g_counts[i] : 0;
    sm[threadIdx.x] = v;
    __syncthreads();
    for (int off = 1; off < 1024; off <<= 1) {
        int t = (threadIdx.x >= off) ? sm[threadIdx.x - off] : 0;
        __syncthreads();
        sm[threadIdx.x] += t;
        __syncthreads();
    }
    if (i < NN) g_local[i] = sm[threadIdx.x] - v;   // exclusive
    if (threadIdx.x == 1023) g_blocksums[blockIdx.x] = sm[1023];
}

__global__ void k_scan_top(int nb) {
    __shared__ int sm[64];
    int t = threadIdx.x;
    int v = (t < nb) ? g_blocksums[t] : 0;
    sm[t] = v;
    __syncthreads();
    for (int off = 1; off < 64; off <<= 1) {
        int u = (t >= off) ? sm[t - off] : 0;
        __syncthreads();
        sm[t] += u;
        __syncthreads();
    }
    if (t < nb) g_blocksums[t] = sm[t] - v;         // exclusive
}

__global__ void k_finalize_csr() {
    int i = blockIdx.x * blockDim.x + threadIdx.x;
    if (i < NN) {
        int off = g_local[i] + g_blocksums[i >> 10];
        g_rowptr[i] = off;
        g_cursor[i] = off + 1;      // slot 0 reserved for self loop
        g_srcarr[off] = i;          // self loop
    }
    if (i == 0) g_rowptr[NN] = TOT;
}

__global__ void k_scatter(const int* __restrict__ ei) {
    int e = blockIdx.x * blockDim.x + threadIdx.x;
    if (e < EE) {
        int s = ei[e];
        int d = ei[EE + e];
        int pos = atomicAdd(&g_cursor[d], 1);
        g_srcarr[pos] = s;
    }
}

// ---------------- tf32 tensor-core dual GEMM (R5 configuration) ----------------
// Grid: 2 * ceil(M/128) blocks; lower half -> B1/xl, upper half -> B2/xr.
__device__ __forceinline__ uint32_t to_tf32(float x) {
    uint32_t r;
    asm("cvt.rna.tf32.f32 %0, %1;" : "=r"(r) : "f"(x));
    return r;
}

#define AS_STRIDE 20
#define BS_STRIDE 136

__global__ void __launch_bounds__(256, 2)
k_mma_dual(const float* __restrict__ Aext, int Asel,
           const float* __restrict__ B1, const float* __restrict__ B2,
           int M, int K) {
    const float* __restrict__ A = (Asel < 0) ? Aext : buf(Asel);

    const int nb   = gridDim.x >> 1;
    const int half = (blockIdx.x >= nb) ? 1 : 0;
    const int blk  = blockIdx.x - half * nb;
    const float* __restrict__ B = half ? B2 : B1;
    float* __restrict__ C = half ? g_xr : g_xl;

    __shared__ uint32_t As[2][128 * AS_STRIDE];
    __shared__ uint32_t Bs[2][16 * BS_STRIDE];

    const int tid  = threadIdx.x;
    const int wid  = tid >> 5;
    const int lane = tid & 31;
    const int g = lane >> 2;
    const int t = lane & 3;
    const int warpM = wid & 1;
    const int warpN = wid >> 1;
    const int row0 = blk * 128;

    float acc[4][4][4];
    #pragma unroll
    for (int i = 0; i < 4; i++)
        #pragma unroll
        for (int j = 0; j < 4; j++)
            #pragma unroll
            for (int k = 0; k < 4; k++) acc[i][j][k] = 0.f;

    float4 ra[2], rb[2];

    // ---- load tile 0 ----
    #pragma unroll
    for (int i = 0; i < 2; i++) {
        int idx = tid + i * 256;
        int r  = idx >> 2, kq = idx & 3;
        int gr = row0 + r;
        ra[i] = (gr < M) ? *reinterpret_cast<const float4*>(&A[(size_t)gr * K + kq * 4])
                         : make_float4(0.f, 0.f, 0.f, 0.f);
        int kk = idx >> 5, nq = idx & 31;
        rb[i] = *reinterpret_cast<const float4*>(&B[(size_t)kk * 128 + nq * 4]);
    }
    #pragma unroll
    for (int i = 0; i < 2; i++) {
        int idx = tid + i * 256;
        int r  = idx >> 2, kq = idx & 3;
        uint32_t* da = &As[0][r * AS_STRIDE + kq * 4];
        da[0] = to_tf32(ra[i].x); da[1] = to_tf32(ra[i].y);
        da[2] = to_tf32(ra[i].z); da[3] = to_tf32(ra[i].w);
        int kk = idx >> 5, nq = idx & 31;
        uint32_t* db = &Bs[0][kk * BS_STRIDE + nq * 4];
        db[0] = to_tf32(rb[i].x); db[1] = to_tf32(rb[i].y);
        db[2] = to_tf32(rb[i].z); db[3] = to_tf32(rb[i].w);
    }
    __syncthreads();

    const int niter = K >> 4;
    int cur = 0;
    for (int it = 0; it < niter; it++) {
        const bool has_next = (it + 1 < niter);
        const int k0n = (it + 1) << 4;
        if (has_next) {
            #pragma unroll
            for (int i = 0; i < 2; i++) {
                int idx = tid + i * 256;
                int r  = idx >> 2, kq = idx & 3;
                int gr = row0 + r;
                ra[i] = (gr < M) ? *reinterpret_cast<const float4*>(&A[(size_t)gr * K + k0n + kq * 4])
                                 : make_float4(0.f, 0.f, 0.f, 0.f);
                int kk = idx >> 5, nq = idx & 31;
                rb[i] = *reinterpret_cast<const float4*>(&B[(size_t)(k0n + kk) * 128 + nq * 4]);
            }
        }

        const uint32_t* __restrict__ Ab = As[cur];
        const uint32_t* __restrict__ Bb = Bs[cur];
        #pragma unroll
        for (int ks = 0; ks < 16; ks += 8) {
            uint32_t afr[4][4];
            #pragma unroll
            for (int mt = 0; mt < 4; mt++) {
                int rowb = warpM * 64 + mt * 16;
                afr[mt][0] = Ab[(rowb + g)     * AS_STRIDE + ks + t];
                afr[mt][1] = Ab[(rowb + g + 8) * AS_STRIDE + ks + t];
                afr[mt][2] = Ab[(rowb + g)     * AS_STRIDE + ks + t + 4];
                afr[mt][3] = Ab[(rowb + g + 8) * AS_STRIDE + ks + t + 4];
            }
            uint32_t bfr[4][2];
            #pragma unroll
            for (int nt = 0; nt < 4; nt++) {
                int nbase = warpN * 32 + nt * 8;
                bfr[nt][0] = Bb[(ks + t)     * BS_STRIDE + nbase + g];
                bfr[nt][1] = Bb[(ks + t + 4) * BS_STRIDE + nbase + g];
            }
            #pragma unroll
            for (int mt = 0; mt < 4; mt++)
                #pragma unroll
                for (int nt = 0; nt < 4; nt++) {
                    asm volatile(
                        "mma.sync.aligned.m16n8k8.row.col.f32.tf32.tf32.f32 "
                        "{%0,%1,%2,%3}, {%4,%5,%6,%7}, {%8,%9}, {%0,%1,%2,%3};"
                        : "+f"(acc[mt][nt][0]), "+f"(acc[mt][nt][1]),
                          "+f"(acc[mt][nt][2]), "+f"(acc[mt][nt][3])
                        : "r"(afr[mt][0]), "r"(afr[mt][1]), "r"(afr[mt][2]), "r"(afr[mt][3]),
                          "r"(bfr[nt][0]), "r"(bfr[nt][1]));
                }
        }

        if (has_next) {
            int nxt = cur ^ 1;
            #pragma unroll
            for (int i = 0; i < 2; i++) {
                int idx = tid + i * 256;
                int r  = idx >> 2, kq = idx & 3;
                uint32_t* da = &As[nxt][r * AS_STRIDE + kq * 4];
                da[0] = to_tf32(ra[i].x); da[1] = to_tf32(ra[i].y);
                da[2] = to_tf32(ra[i].z); da[3] = to_tf32(ra[i].w);
                int kk = idx >> 5, nq = idx & 31;
                uint32_t* db = &Bs[nxt][kk * BS_STRIDE + nq * 4];
                db[0] = to_tf32(rb[i].x); db[1] = to_tf32(rb[i].y);
                db[2] = to_tf32(rb[i].z); db[3] = to_tf32(rb[i].w);
            }
        }
        __syncthreads();
        cur ^= 1;
    }

    // epilogue
    #pragma unroll
    for (int mt = 0; mt < 4; mt++) {
        int r0 = row0 + warpM * 64 + mt * 16 + g;
        #pragma unroll
        for (int nt = 0; nt < 4; nt++) {
            int c = warpN * 32 + nt * 8 + t * 2;
            if (r0 < M)
                *reinterpret_cast<float2*>(&C[(size_t)r0 * 128 + c]) =
                    make_float2(acc[mt][nt][0], acc[mt][nt][1]);
            if (r0 + 8 < M)
                *reinterpret_cast<float2*>(&C[(size_t)(r0 + 8) * 128 + c]) =
                    make_float2(acc[mt][nt][2], acc[mt][nt][3]);
        }
    }
}

// ---------------- GATv2 aggregation: warp/node, DUAL online-softmax states ----------------
__device__ __forceinline__ float lrelu(float v) { return v > 0.f ? v : NEG_SLOPE * v; }

__device__ __forceinline__ void osm_update(float& m, float& s, float4& acc,
                                           float eh, const float4& xlv) {
    if (eh > m) {
        float sc = __expf(m - eh);
        s *= sc;
        acc.x *= sc; acc.y *= sc; acc.z *= sc; acc.w *= sc;
        m = eh;
    }
    float w = __expf(eh - m);
    s += w;
    acc.x += w * xlv.x; acc.y += w * xlv.y;
    acc.z += w * xlv.z; acc.w += w * xlv.w;
}

__global__ void k_aggregate(const float* __restrict__ att, const float* __restrict__ bias,
                            int outsel, int do_relu) {
    int warp = (blockIdx.x * blockDim.x + threadIdx.x) >> 5;
    if (warp >= NN) return;
    int lane = threadIdx.x & 31;
    const float* __restrict__ xl = g_xl;
    const float* __restrict__ xr = g_xr;
    float* __restrict__ out = buf(outsel);

    const float4 xrv  = *reinterpret_cast<const float4*>(&xr[(size_t)warp * HD + lane * 4]);
    const float4 attv = *reinterpret_cast<const float4*>(&att[lane * 4]);

    // two independent online-softmax states (even edges -> 0, odd -> 1)
    float m0 = -1e30f, s0 = 0.f, m1 = -1e30f, s1 = 0.f;
    float4 a0 = make_float4(0.f, 0.f, 0.f, 0.f);
    float4 a1 = make_float4(0.f, 0.f, 0.f, 0.f);

    const int beg = g_rowptr[warp];
    const int end = g_rowptr[warp + 1];

    int e = beg;
    for (; e + 1 < end; e += 2) {
        int sA = g_srcarr[e];
        int sB = g_srcarr[e + 1];
        const float4 xA = *reinterpret_cast<const float4*>(&xl[(size_t)sA * HD + lane * 4]);
        const float4 xB = *reinterpret_cast<const float4*>(&xl[(size_t)sB * HD + lane * 4]);

        float pA = lrelu(xA.x + xrv.x) * attv.x
                 + lrelu(xA.y + xrv.y) * attv.y
                 + lrelu(xA.z + xrv.z) * attv.z
                 + lrelu(xA.w + xrv.w) * attv.w;
        float pB = lrelu(xB.x + xrv.x) * attv.x
                 + lrelu(xB.y + xrv.y) * attv.y
                 + lrelu(xB.z + xrv.z) * attv.z
                 + lrelu(xB.w + xrv.w) * attv.w;
        pA += __shfl_xor_sync(0xffffffffu, pA, 1);
        pB += __shfl_xor_sync(0xffffffffu, pB, 1);
        pA += __shfl_xor_sync(0xffffffffu, pA, 2);
        pB += __shfl_xor_sync(0xffffffffu, pB, 2);
        pA += __shfl_xor_sync(0xffffffffu, pA, 4);
        pB += __shfl_xor_sync(0xffffffffu, pB, 4);

        osm_update(m0, s0, a0, pA, xA);
        osm_update(m1, s1, a1, pB, xB);
    }
    if (e < end) {
        int sA = g_srcarr[e];
        const float4 xA = *reinterpret_cast<const float4*>(&xl[(size_t)sA * HD + lane * 4]);
        float pA = lrelu(xA.x + xrv.x) * attv.x
                 + lrelu(xA.y + xrv.y) * attv.y
                 + lrelu(xA.z + xrv.z) * attv.z
                 + lrelu(xA.w + xrv.w) * attv.w;
        pA += __shfl_xor_sync(0xffffffffu, pA, 1);
        pA += __shfl_xor_sync(0xffffffffu, pA, 2);
        pA += __shfl_xor_sync(0xffffffffu, pA, 4);
        osm_update(m0, s0, a0, pA, xA);
    }

    // merge the two states (exact)
    float m = fmaxf(m0, m1);
    float c0 = __expf(m0 - m);   // state0 always non-empty (self-loop)
    float c1 = (s1 > 0.f) ? __expf(m1 - m) : 0.f;
    float s = s0 * c0 + s1 * c1;
    float4 acc;
    acc.x = a0.x * c0 + a1.x * c1;
    acc.y = a0.y * c0 + a1.y * c1;
    acc.z = a0.z * c0 + a1.z * c1;
    acc.w = a0.w * c0 + a1.w * c1;

    float inv = 1.f / (s + 1e-16f);
    const float4 bv = *reinterpret_cast<const float4*>(&bias[lane * 4]);
    float4 o;
    o.x = acc.x * inv + bv.x;
    o.y = acc.y * inv + bv.y;
    o.z = acc.z * inv + bv.z;
    o.w = acc.w * inv + bv.w;
    if (do_relu) {
        o.x = fmaxf(o.x, 0.f); o.y = fmaxf(o.y, 0.f);
        o.z = fmaxf(o.z, 0.f); o.w = fmaxf(o.w, 0.f);
    }
    *reinterpret_cast<float4*>(&out[(size_t)warp * HD + lane * 4]) = o;
}

// ---------------- pooling + classifier ----------------
__global__ void k_pool(int hsel) {
    const float* __restrict__ h = buf(hsel);
    int col = threadIdx.x;   // blockDim = 128
    float acc = 0.f;
    for (int r = blockIdx.x; r < NN; r += gridDim.x)
        acc += h[(size_t)r * HD + col];
    atomicAdd(&g_pool[col], acc);
}

__global__ void k_classify(const float* __restrict__ W, const float* __restrict__ b,
                           float* __restrict__ out) {
    int j = threadIdx.x;
    if (j < 2) {
        float s = 0.f;
        const float invn = 1.f / (float)NN;
        for (int k = 0; k < HD; k++)
            s += g_pool[k] * invn * W[k * 2 + j];
        out[j] = s + b[j];
    }
}

// ---------------- launch ----------------
extern "C" void kernel_launch(void* const* d_in, const int* in_sizes, int n_in,
                              void* d_out, int out_size) {
    const float* x  = (const float*)d_in[0];
    const int*   ei = (const int*)d_in[1];   // delivered as int32 (JAX x64 disabled)
    const float* Wl[4]  = {(const float*)d_in[2],  (const float*)d_in[6],
                           (const float*)d_in[10], (const float*)d_in[14]};
    const float* Wr[4]  = {(const float*)d_in[3],  (const float*)d_in[7],
                           (const float*)d_in[11], (const float*)d_in[15]};
    const float* att[4] = {(const float*)d_in[4],  (const float*)d_in[8],
                           (const float*)d_in[12], (const float*)d_in[16]};
    const float* bia[4] = {(const float*)d_in[5],  (const float*)d_in[9],
                           (const float*)d_in[13], (const float*)d_in[17]};
    const float* clfW = (const float*)d_in[18];
    const float* clfb = (const float*)d_in[19];
    float* out = (float*)d_out;

    const int TB = 256;
    const int gN  = (NN + TB - 1) / TB;
    const int gE  = (EE + TB - 1) / TB;
    const int gSc = (NN + 1023) / 1024;            // 49
    const int gGm = 2 * ((NN + 127) / 128);        // 782 (dual, split halves)
    const int gAg = (NN * 32 + TB - 1) / TB;       // warp per node

    // CSR by dst (rebuilt every call: deterministic work)
    k_init<<<gN, TB>>>();
    k_hist<<<gE, TB>>>(ei);
    k_scan_block<<<gSc, 1024>>>();
    k_scan_top<<<1, 64>>>(gSc);
    k_finalize_csr<<<gN, TB>>>();
    k_scatter<<<gE, TB>>>(ei);

    // layer 1 (K=768): A = external x
    k_mma_dual<<<gGm, TB>>>(x, -1, Wl[0], Wr[0], NN, FIN);
    k_aggregate<<<gAg, TB>>>(att[0], bia[0], 2, 1);
    // layer 2: A = hA(2)
    k_mma_dual<<<gGm, TB>>>(nullptr, 2, Wl[1], Wr[1], NN, HD);
    k_aggregate<<<gAg, TB>>>(att[1], bia[1], 3, 1);
    // layer 3: A = hB(3)
    k_mma_dual<<<gGm, TB>>>(nullptr, 3, Wl[2], Wr[2], NN, HD);
    k_aggregate<<<gAg, TB>>>(att[2], bia[2], 2, 1);
    // layer 4 (no relu): A = hA(2)
    k_mma_dual<<<gGm, TB>>>(nullptr, 2, Wl[3], Wr[3], NN, HD);
    k_aggregate<<<gAg, TB>>>(att[3], bia[3], 3, 0);

    // mean-pool + classifier
    k_pool<<<512, 128>>>(3);
    k_classify<<<1, 32>>>(clfW, clfb, out);
}

// round 10
// speedup vs baseline: 1.0439x; 1.0067x over previous
#include <cuda_runtime.h>
#include <cuda_fp16.h>
#include <cstdint>

#define NN 50000
#define EE 640000
#define FIN 768
#define HD 128
#define TOT (EE + NN)
#define NEG_SLOPE 0.2f

// ---------------- scratch (device globals; no allocation allowed) ----------------
__device__ __half g_xlh[NN * HD];   // xl in fp16 (only consumer: aggregation)
__device__ float  g_xr[NN * HD];
__device__ float  g_hA[NN * HD];
__device__ float  g_hB[NN * HD];
__device__ int    g_counts[NN];
__device__ int    g_local[NN];
__device__ int    g_rowptr[NN + 1];
__device__ int    g_cursor[NN];
__device__ int    g_srcarr[TOT];
__device__ int    g_blocksums[64];
__device__ float  g_pool[HD];

// buffer selector for fp32 node-feature buffers: 2=hA 3=hB
__device__ __forceinline__ float* buf(int i) {
    return i == 2 ? g_hA : g_hB;
}

// ---------------- CSR build ----------------
__global__ void k_init() {
    int i = blockIdx.x * blockDim.x + threadIdx.x;
    if (i < NN) g_counts[i] = 1;          // self loop
    if (i < HD) g_pool[i] = 0.f;
}

__global__ void k_hist(const int* __restrict__ ei) {
    int e = blockIdx.x * blockDim.x + threadIdx.x;
    if (e < EE) atomicAdd(&g_counts[ei[EE + e]], 1);
}

__global__ void k_scan_block() {
    __shared__ int sm[1024];
    int i = blockIdx.x * 1024 + threadIdx.x;
    int v = (i < NN) ? g_counts[i] : 0;
    sm[threadIdx.x] = v;
    __syncthreads();
    for (int off = 1; off < 1024; off <<= 1) {
        int t = (threadIdx.x >= off) ? sm[threadIdx.x - off] : 0;
        __syncthreads();
        sm[threadIdx.x] += t;
        __syncthreads();
    }
    if (i < NN) g_local[i] = sm[threadIdx.x] - v;   // exclusive
    if (threadIdx.x == 1023) g_blocksums[blockIdx.x] = sm[1023];
}

__global__ void k_scan_top(int nb) {
    __shared__ int sm[64];
    int t = threadIdx.x;
    int v = (t < nb) ? g_blocksums[t] : 0;
    sm[t] = v;
    __syncthreads();
    for (int off = 1; off < 64; off <<= 1) {
        int u = (t >= off) ? sm[t - off] : 0;
        __syncthreads();
        sm[t] += u;
        __syncthreads();
    }
    if (t < nb) g_blocksums[t] = sm[t] - v;         // exclusive
}

__global__ void k_finalize_csr() {
    int i = blockIdx.x * blockDim.x + threadIdx.x;
    if (i < NN) {
        int off = g_local[i] + g_blocksums[i >> 10];
        g_rowptr[i] = off;
        g_cursor[i] = off + 1;      // slot 0 reserved for self loop
        g_srcarr[off] = i;          // self loop
    }
    if (i == 0) g_rowptr[NN] = TOT;
}

__global__ void k_scatter(const int* __restrict__ ei) {
    int e = blockIdx.x * blockDim.x + threadIdx.x;
    if (e < EE) {
        int s = ei[e];
        int d = ei[EE + e];
        g_srcarr[atomicAdd(&g_cursor[d], 1)] = s;
    }
}

// ---------------- tf32 tensor-core dual GEMM (R5 config; xl epilogue -> fp16) ----------------
// Grid: 2 * ceil(M/128); lower half -> B1 -> g_xlh (fp16), upper half -> B2 -> g_xr (fp32).
__device__ __forceinline__ uint32_t to_tf32(float x) {
    uint32_t r;
    asm("cvt.rna.tf32.f32 %0, %1;" : "=r"(r) : "f"(x));
    return r;
}

#define AS_STRIDE 20
#define BS_STRIDE 136

__global__ void __launch_bounds__(256, 2)
k_mma_dual(const float* __restrict__ Aext, int Asel,
           const float* __restrict__ B1, const float* __restrict__ B2,
           int M, int K) {
    const float* __restrict__ A = (Asel < 0) ? Aext : buf(Asel);

    const int nb   = gridDim.x >> 1;
    const int half = (blockIdx.x >= nb) ? 1 : 0;
    const int blk  = blockIdx.x - half * nb;
    const float* __restrict__ B = half ? B2 : B1;

    __shared__ uint32_t As[2][128 * AS_STRIDE];
    __shared__ uint32_t Bs[2][16 * BS_STRIDE];

    const int tid  = threadIdx.x;
    const int wid  = tid >> 5;
    const int lane = tid & 31;
    const int g = lane >> 2;
    const int t = lane & 3;
    const int warpM = wid & 1;
    const int warpN = wid >> 1;
    const int row0 = blk * 128;

    float acc[4][4][4];
    #pragma unroll
    for (int i = 0; i < 4; i++)
        #pragma unroll
        for (int j = 0; j < 4; j++)
            #pragma unroll
            for (int k = 0; k < 4; k++) acc[i][j][k] = 0.f;

    float4 ra[2], rb[2];

    // ---- load tile 0 ----
    #pragma unroll
    for (int i = 0; i < 2; i++) {
        int idx = tid + i * 256;
        int r  = idx >> 2, kq = idx & 3;
        int gr = row0 + r;
        ra[i] = (gr < M) ? *reinterpret_cast<const float4*>(&A[(size_t)gr * K + kq * 4])
                         : make_float4(0.f, 0.f, 0.f, 0.f);
        int kk = idx >> 5, nq = idx & 31;
        rb[i] = *reinterpret_cast<const float4*>(&B[(size_t)kk * 128 + nq * 4]);
    }
    #pragma unroll
    for (int i = 0; i < 2; i++) {
        int idx = tid + i * 256;
        int r  = idx >> 2, kq = idx & 3;
        uint32_t* da = &As[0][r * AS_STRIDE + kq * 4];
        da[0] = to_tf32(ra[i].x); da[1] = to_tf32(ra[i].y);
        da[2] = to_tf32(ra[i].z); da[3] = to_tf32(ra[i].w);
        int kk = idx >> 5, nq = idx & 31;
        uint32_t* db = &Bs[0][kk * BS_STRIDE + nq * 4];
        db[0] = to_tf32(rb[i].x); db[1] = to_tf32(rb[i].y);
        db[2] = to_tf32(rb[i].z); db[3] = to_tf32(rb[i].w);
    }
    __syncthreads();

    const int niter = K >> 4;
    int cur = 0;
    for (int it = 0; it < niter; it++) {
        const bool has_next = (it + 1 < niter);
        const int k0n = (it + 1) << 4;
        if (has_next) {
            #pragma unroll
            for (int i = 0; i < 2; i++) {
                int idx = tid + i * 256;
                int r  = idx >> 2, kq = idx & 3;
                int gr = row0 + r;
                ra[i] = (gr < M) ? *reinterpret_cast<const float4*>(&A[(size_t)gr * K + k0n + kq * 4])
                                 : make_float4(0.f, 0.f, 0.f, 0.f);
                int kk = idx >> 5, nq = idx & 31;
                rb[i] = *reinterpret_cast<const float4*>(&B[(size_t)(k0n + kk) * 128 + nq * 4]);
            }
        }

        const uint32_t* __restrict__ Ab = As[cur];
        const uint32_t* __restrict__ Bb = Bs[cur];
        #pragma unroll
        for (int ks = 0; ks < 16; ks += 8) {
            uint32_t afr[4][4];
            #pragma unroll
            for (int mt = 0; mt < 4; mt++) {
                int rowb = warpM * 64 + mt * 16;
                afr[mt][0] = Ab[(rowb + g)     * AS_STRIDE + ks + t];
                afr[mt][1] = Ab[(rowb + g + 8) * AS_STRIDE + ks + t];
                afr[mt][2] = Ab[(rowb + g)     * AS_STRIDE + ks + t + 4];
                afr[mt][3] = Ab[(rowb + g + 8) * AS_STRIDE + ks + t + 4];
            }
            uint32_t bfr[4][2];
            #pragma unroll
            for (int nt = 0; nt < 4; nt++) {
                int nbase = warpN * 32 + nt * 8;
                bfr[nt][0] = Bb[(ks + t)     * BS_STRIDE + nbase + g];
                bfr[nt][1] = Bb[(ks + t + 4) * BS_STRIDE + nbase + g];
            }
            #pragma unroll
            for (int mt = 0; mt < 4; mt++)
                #pragma unroll
                for (int nt = 0; nt < 4; nt++) {
                    asm volatile(
                        "mma.sync.aligned.m16n8k8.row.col.f32.tf32.tf32.f32 "
                        "{%0,%1,%2,%3}, {%4,%5,%6,%7}, {%8,%9}, {%0,%1,%2,%3};"
                        : "+f"(acc[mt][nt][0]), "+f"(acc[mt][nt][1]),
                          "+f"(acc[mt][nt][2]), "+f"(acc[mt][nt][3])
                        : "r"(afr[mt][0]), "r"(afr[mt][1]), "r"(afr[mt][2]), "r"(afr[mt][3]),
                          "r"(bfr[nt][0]), "r"(bfr[nt][1]));
                }
        }

        if (has_next) {
            int nxt = cur ^ 1;
            #pragma unroll
            for (int i = 0; i < 2; i++) {
                int idx = tid + i * 256;
                int r  = idx >> 2, kq = idx & 3;
                uint32_t* da = &As[nxt][r * AS_STRIDE + kq * 4];
                da[0] = to_tf32(ra[i].x); da[1] = to_tf32(ra[i].y);
                da[2] = to_tf32(ra[i].z); da[3] = to_tf32(ra[i].w);
                int kk = idx >> 5, nq = idx & 31;
                uint32_t* db = &Bs[nxt][kk * BS_STRIDE + nq * 4];
                db[0] = to_tf32(rb[i].x); db[1] = to_tf32(rb[i].y);
                db[2] = to_tf32(rb[i].z); db[3] = to_tf32(rb[i].w);
            }
        }
        __syncthreads();
        cur ^= 1;
    }

    // epilogue: half 0 -> g_xlh (fp16), half 1 -> g_xr (fp32)
    #pragma unroll
    for (int mt = 0; mt < 4; mt++) {
        int r0 = row0 + warpM * 64 + mt * 16 + g;
        #pragma unroll
        for (int nt = 0; nt < 4; nt++) {
            int c = warpN * 32 + nt * 8 + t * 2;
            if (half) {
                if (r0 < M)
                    *reinterpret_cast<float2*>(&g_xr[(size_t)r0 * 128 + c]) =
                        make_float2(acc[mt][nt][0], acc[mt][nt][1]);
                if (r0 + 8 < M)
                    *reinterpret_cast<float2*>(&g_xr[(size_t)(r0 + 8) * 128 + c]) =
                        make_float2(acc[mt][nt][2], acc[mt][nt][3]);
            } else {
                if (r0 < M)
                    *reinterpret_cast<__half2*>(&g_xlh[(size_t)r0 * 128 + c]) =
                        __floats2half2_rn(acc[mt][nt][0], acc[mt][nt][1]);
                if (r0 + 8 < M)
                    *reinterpret_cast<__half2*>(&g_xlh[(size_t)(r0 + 8) * 128 + c]) =
                        __floats2half2_rn(acc[mt][nt][2], acc[mt][nt][3]);
            }
        }
    }
}

// ---------------- GATv2 aggregation: warp/node, dual softmax states, fp16 gathers ----------------
__device__ __forceinline__ float lrelu(float v) { return v > 0.f ? v : NEG_SLOPE * v; }

__device__ __forceinline__ void osm_update(float& m, float& s, float4& acc,
                                           float eh, const float4& xlv) {
    if (eh > m) {
        float sc = __expf(m - eh);
        s *= sc;
        acc.x *= sc; acc.y *= sc; acc.z *= sc; acc.w *= sc;
        m = eh;
    }
    float w = __expf(eh - m);
    s += w;
    acc.x += w * xlv.x; acc.y += w * xlv.y;
    acc.z += w * xlv.z; acc.w += w * xlv.w;
}

__device__ __forceinline__ float4 load_xl_h(const __half* xlh, int node, int lane) {
    const uint2 raw = *reinterpret_cast<const uint2*>(&xlh[(size_t)node * HD + lane * 4]);
    float2 f0 = __half22float2(*reinterpret_cast<const __half2*>(&raw.x));
    float2 f1 = __half22float2(*reinterpret_cast<const __half2*>(&raw.y));
    return make_float4(f0.x, f0.y, f1.x, f1.y);
}

__global__ void k_aggregate(const float* __restrict__ att, const float* __restrict__ bias,
                            int outsel, int do_relu) {
    int warp = (blockIdx.x * blockDim.x + threadIdx.x) >> 5;
    if (warp >= NN) return;
    int lane = threadIdx.x & 31;
    const __half* __restrict__ xlh = g_xlh;
    float* __restrict__ out = buf(outsel);

    const float4 xrv  = *reinterpret_cast<const float4*>(&g_xr[(size_t)warp * HD + lane * 4]);
    const float4 attv = *reinterpret_cast<const float4*>(&att[lane * 4]);

    float m0 = -1e30f, s0 = 0.f, m1 = -1e30f, s1 = 0.f;
    float4 a0 = make_float4(0.f, 0.f, 0.f, 0.f);
    float4 a1 = make_float4(0.f, 0.f, 0.f, 0.f);

    const int beg = g_rowptr[warp];
    const int end = g_rowptr[warp + 1];

    int e = beg;
    for (; e + 1 < end; e += 2) {
        int sA = g_srcarr[e];
        int sB = g_srcarr[e + 1];
        const float4 xA = load_xl_h(xlh, sA, lane);
        const float4 xB = load_xl_h(xlh, sB, lane);

        float pA = lrelu(xA.x + xrv.x) * attv.x + lrelu(xA.y + xrv.y) * attv.y
                 + lrelu(xA.z + xrv.z) * attv.z + lrelu(xA.w + xrv.w) * attv.w;
        float pB = lrelu(xB.x + xrv.x) * attv.x + lrelu(xB.y + xrv.y) * attv.y
                 + lrelu(xB.z + xrv.z) * attv.z + lrelu(xB.w + xrv.w) * attv.w;
        pA += __shfl_xor_sync(0xffffffffu, pA, 1);
        pB += __shfl_xor_sync(0xffffffffu, pB, 1);
        pA += __shfl_xor_sync(0xffffffffu, pA, 2);
        pB += __shfl_xor_sync(0xffffffffu, pB, 2);
        pA += __shfl_xor_sync(0xffffffffu, pA, 4);
        pB += __shfl_xor_sync(0xffffffffu, pB, 4);

        osm_update(m0, s0, a0, pA, xA);
        osm_update(m1, s1, a1, pB, xB);
    }
    if (e < end) {
        int sA = g_srcarr[e];
        const float4 xA = load_xl_h(xlh, sA, lane);
        float pA = lrelu(xA.x + xrv.x) * attv.x + lrelu(xA.y + xrv.y) * attv.y
                 + lrelu(xA.z + xrv.z) * attv.z + lrelu(xA.w + xrv.w) * attv.w;
        pA += __shfl_xor_sync(0xffffffffu, pA, 1);
        pA += __shfl_xor_sync(0xffffffffu, pA, 2);
        pA += __shfl_xor_sync(0xffffffffu, pA, 4);
        osm_update(m0, s0, a0, pA, xA);
    }

    // merge the two states (exact)
    float m = fmaxf(m0, m1);
    float c0 = __expf(m0 - m);
    float c1 = (s1 > 0.f) ? __expf(m1 - m) : 0.f;
    float s = s0 * c0 + s1 * c1;
    float4 acc;
    acc.x = a0.x * c0 + a1.x * c1;
    acc.y = a0.y * c0 + a1.y * c1;
    acc.z = a0.z * c0 + a1.z * c1;
    acc.w = a0.w * c0 + a1.w * c1;

    float inv = 1.f / (s + 1e-16f);
    const float4 bv = *reinterpret_cast<const float4*>(&bias[lane * 4]);
    float4 o;
    o.x = acc.x * inv + bv.x;
    o.y = acc.y * inv + bv.y;
    o.z = acc.z * inv + bv.z;
    o.w = acc.w * inv + bv.w;
    if (do_relu) {
        o.x = fmaxf(o.x, 0.f); o.y = fmaxf(o.y, 0.f);
        o.z = fmaxf(o.z, 0.f); o.w = fmaxf(o.w, 0.f);
    }
    *reinterpret_cast<float4*>(&out[(size_t)warp * HD + lane * 4]) = o;
}

// ---------------- pooling + classifier ----------------
__global__ void k_pool(int hsel) {
    const float* __restrict__ h = buf(hsel);
    int col = threadIdx.x;   // blockDim = 128
    float acc = 0.f;
    for (int r = blockIdx.x; r < NN; r += gridDim.x)
        acc += h[(size_t)r * HD + col];
    atomicAdd(&g_pool[col], acc);
}

__global__ void k_classify(const float* __restrict__ W, const float* __restrict__ b,
                           float* __restrict__ out) {
    int j = threadIdx.x;
    if (j < 2) {
        float s = 0.f;
        const float invn = 1.f / (float)NN;
        for (int k = 0; k < HD; k++)
            s += g_pool[k] * invn * W[k * 2 + j];
        out[j] = s + b[j];
    }
}

// ---------------- launch ----------------
extern "C" void kernel_launch(void* const* d_in, const int* in_sizes, int n_in,
                              void* d_out, int out_size) {
    const float* x  = (const float*)d_in[0];
    const int*   ei = (const int*)d_in[1];   // int32 (JAX x64 disabled)
    const float* Wl[4]  = {(const float*)d_in[2],  (const float*)d_in[6],
                           (const float*)d_in[10], (const float*)d_in[14]};
    const float* Wr[4]  = {(const float*)d_in[3],  (const float*)d_in[7],
                           (const float*)d_in[11], (const float*)d_in[15]};
    const float* att[4] = {(const float*)d_in[4],  (const float*)d_in[8],
                           (const float*)d_in[12], (const float*)d_in[16]};
    const float* bia[4] = {(const float*)d_in[5],  (const float*)d_in[9],
                           (const float*)d_in[13], (const float*)d_in[17]};
    const float* clfW = (const float*)d_in[18];
    const float* clfb = (const float*)d_in[19];
    float* out = (float*)d_out;

    const int TB = 256;
    const int gN  = (NN + TB - 1) / TB;
    const int gE  = (EE + TB - 1) / TB;
    const int gSc = (NN + 1023) / 1024;            // 49
    const int gGm = 2 * ((NN + 127) / 128);        // 782 (dual, split halves)
    const int gAg = (NN * 32 + TB - 1) / TB;       // warp per node

    // CSR by dst (rebuilt every call: deterministic work)
    k_init<<<gN, TB>>>();
    k_hist<<<gE, TB>>>(ei);
    k_scan_block<<<gSc, 1024>>>();
    k_scan_top<<<1, 64>>>(gSc);
    k_finalize_csr<<<gN, TB>>>();
    k_scatter<<<gE, TB>>>(ei);

    // layer 1 (K=768): A = external x
    k_mma_dual<<<gGm, TB>>>(x, -1, Wl[0], Wr[0], NN, FIN);
    k_aggregate<<<gAg, TB>>>(att[0], bia[0], 2, 1);
    // layer 2: A = hA(2)
    k_mma_dual<<<gGm, TB>>>(nullptr, 2, Wl[1], Wr[1], NN, HD);
    k_aggregate<<<gAg, TB>>>(att[1], bia[1], 3, 1);
    // layer 3: A = hB(3)
    k_mma_dual<<<gGm, TB>>>(nullptr, 3, Wl[2], Wr[2], NN, HD);
    k_aggregate<<<gAg, TB>>>(att[2], bia[2], 2, 1);
    // layer 4 (no relu): A = hA(2)
    k_mma_dual<<<gGm, TB>>>(nullptr, 2, Wl[3], Wr[3], NN, HD);
    k_aggregate<<<gAg, TB>>>(att[3], bia[3], 3, 0);

    // mean-pool + classifier
    k_pool<<<512, 128>>>(3);
    k_classify<<<1, 32>>>(clfW, clfb, out);
}

// round 11
// speedup vs baseline: 1.2493x; 1.1967x over previous
#include <cuda_runtime.h>
#include <cuda_fp16.h>
#include <cstdint>

#define NN 50000
#define EE 640000
#define FIN 768
#define HD 128
#define TOT (EE + NN)
#define NEG_SLOPE 0.2f

// ---------------- scratch (device globals; no allocation allowed) ----------------
__device__ __half g_xlh[NN * HD];   // xl in fp16 (only consumer: aggregation)
__device__ float  g_xr[NN * HD];
__device__ float  g_hA[NN * HD];
__device__ float  g_hB[NN * HD];
__device__ int    g_counts[NN];
__device__ int    g_local[NN];
__device__ int    g_rowptr[NN + 1];
__device__ int    g_cursor[NN];
__device__ int    g_srcarr[TOT];
__device__ int    g_blocksums[64];
__device__ float  g_pool[HD];

// buffer selector for fp32 node-feature buffers: 2=hA 3=hB
__device__ __forceinline__ float* buf(int i) {
    return i == 2 ? g_hA : g_hB;
}

// ---------------- CSR build ----------------
__global__ void k_init() {
    int i = blockIdx.x * blockDim.x + threadIdx.x;
    if (i < NN) g_counts[i] = 1;          // self loop
    if (i < HD) g_pool[i] = 0.f;
}

__global__ void k_hist(const int* __restrict__ ei) {
    int e = blockIdx.x * blockDim.x + threadIdx.x;
    if (e < EE) atomicAdd(&g_counts[ei[EE + e]], 1);
}

__global__ void k_scan_block() {
    __shared__ int sm[1024];
    int i = blockIdx.x * 1024 + threadIdx.x;
    int v = (i < NN) ? g_counts[i] : 0;
    sm[threadIdx.x] = v;
    __syncthreads();
    for (int off = 1; off < 1024; off <<= 1) {
        int t = (threadIdx.x >= off) ? sm[threadIdx.x - off] : 0;
        __syncthreads();
        sm[threadIdx.x] += t;
        __syncthreads();
    }
    if (i < NN) g_local[i] = sm[threadIdx.x] - v;   // exclusive
    if (threadIdx.x == 1023) g_blocksums[blockIdx.x] = sm[1023];
}

__global__ void k_scan_top(int nb) {
    __shared__ int sm[64];
    int t = threadIdx.x;
    int v = (t < nb) ? g_blocksums[t] : 0;
    sm[t] = v;
    __syncthreads();
    for (int off = 1; off < 64; off <<= 1) {
        int u = (t >= off) ? sm[t - off] : 0;
        __syncthreads();
        sm[t] += u;
        __syncthreads();
    }
    if (t < nb) g_blocksums[t] = sm[t] - v;         // exclusive
}

__global__ void k_finalize_csr() {
    int i = blockIdx.x * blockDim.x + threadIdx.x;
    if (i < NN) {
        int off = g_local[i] + g_blocksums[i >> 10];
        g_rowptr[i] = off;
        g_cursor[i] = off + 1;      // slot 0 reserved for self loop
        g_srcarr[off] = i;          // self loop
    }
    if (i == 0) g_rowptr[NN] = TOT;
}

__global__ void k_scatter(const int* __restrict__ ei) {
    int e = blockIdx.x * blockDim.x + threadIdx.x;
    if (e < EE) {
        int s = ei[e];
        int d = ei[EE + e];
        g_srcarr[atomicAdd(&g_cursor[d], 1)] = s;
    }
}

// ---------------- fp16 tensor-core dual GEMM (m16n8k16, fp32 accum) ----------------
// Grid: 2 * ceil(M/128); lower half -> B1 -> g_xlh (fp16), upper half -> B2 -> g_xr (fp32).
// K-chunk 32, double-buffered. A/weights converted fp32->fp16 at staging.
__device__ __forceinline__ uint32_t pack_h2(float a, float b) {
    __half2 h = __floats2half2_rn(a, b);
    return *reinterpret_cast<uint32_t*>(&h);
}

#define ASTR 20     // uint32 (half2-pair) stride; bank = 20g+t all-distinct
#define BSTR 136    // bank = 8t+g all-distinct

__global__ void __launch_bounds__(256, 2)
k_mma_dual(const float* __restrict__ Aext, int Asel,
           const float* __restrict__ B1, const float* __restrict__ B2,
           int M, int K) {
    const float* __restrict__ A = (Asel < 0) ? Aext : buf(Asel);

    const int nb   = gridDim.x >> 1;
    const int half = (blockIdx.x >= nb) ? 1 : 0;
    const int blk  = blockIdx.x - half * nb;
    const float* __restrict__ B = half ? B2 : B1;

    // per buffer: A = 128 rows x 16 half2 (k-chunk 32), B = 16 kpairs x 128 cols
    __shared__ uint32_t As[2][128 * ASTR];
    __shared__ uint32_t Bs[2][16 * BSTR];

    const int tid  = threadIdx.x;
    const int wid  = tid >> 5;
    const int lane = tid & 31;
    const int g = lane >> 2;
    const int t = lane & 3;
    const int warpM = wid & 1;   // 2 warps in M (64 rows)
    const int warpN = wid >> 1;  // 4 warps in N (32 cols)
    const int row0 = blk * 128;

    float acc[4][4][4];
    #pragma unroll
    for (int i = 0; i < 4; i++)
        #pragma unroll
        for (int j = 0; j < 4; j++)
            #pragma unroll
            for (int k = 0; k < 4; k++) acc[i][j][k] = 0.f;

    // staging registers for next chunk
    float4 ra[4], rbE[2], rbO[2];

    // indices for staging (constant per thread)
    // A: 1024 float4 slots: slot = tid + i*256 ; r = slot>>3 (0..127), q = slot&7 (k = q*4)
    // B: 512 cells: cell = tid + i*256 ; p = cell>>5 (kpair 0..15), n4 = cell&31

    // ---- load chunk 0 ----
    #pragma unroll
    for (int i = 0; i < 4; i++) {
        int slot = tid + i * 256;
        int r = slot >> 3, q = slot & 7;
        int gr = row0 + r;
        ra[i] = (gr < M) ? *reinterpret_cast<const float4*>(&A[(size_t)gr * K + q * 4])
                         : make_float4(0.f, 0.f, 0.f, 0.f);
    }
    #pragma unroll
    for (int i = 0; i < 2; i++) {
        int cell = tid + i * 256;
        int p = cell >> 5, n4 = cell & 31;
        rbE[i] = *reinterpret_cast<const float4*>(&B[(size_t)(2 * p)     * 128 + n4 * 4]);
        rbO[i] = *reinterpret_cast<const float4*>(&B[(size_t)(2 * p + 1) * 128 + n4 * 4]);
    }
    // store chunk 0 -> buffer 0
    #pragma unroll
    for (int i = 0; i < 4; i++) {
        int slot = tid + i * 256;
        int r = slot >> 3, q = slot & 7;
        uint2 h;
        h.x = pack_h2(ra[i].x, ra[i].y);
        h.y = pack_h2(ra[i].z, ra[i].w);
        *reinterpret_cast<uint2*>(&As[0][r * ASTR + q * 2]) = h;
    }
    #pragma unroll
    for (int i = 0; i < 2; i++) {
        int cell = tid + i * 256;
        int p = cell >> 5, n4 = cell & 31;
        uint4 o;
        o.x = pack_h2(rbE[i].x, rbO[i].x);
        o.y = pack_h2(rbE[i].y, rbO[i].y);
        o.z = pack_h2(rbE[i].z, rbO[i].z);
        o.w = pack_h2(rbE[i].w, rbO[i].w);
        *reinterpret_cast<uint4*>(&Bs[0][p * BSTR + n4 * 4]) = o;
    }
    __syncthreads();

    const int niter = K >> 5;    // k-chunk 32
    int cur = 0;
    for (int it = 0; it < niter; it++) {
        const bool has_next = (it + 1 < niter);
        const int k0n = (it + 1) << 5;
        if (has_next) {
            #pragma unroll
            for (int i = 0; i < 4; i++) {
                int slot = tid + i * 256;
                int r = slot >> 3, q = slot & 7;
                int gr = row0 + r;
                ra[i] = (gr < M) ? *reinterpret_cast<const float4*>(&A[(size_t)gr * K + k0n + q * 4])
                                 : make_float4(0.f, 0.f, 0.f, 0.f);
            }
            #pragma unroll
            for (int i = 0; i < 2; i++) {
                int cell = tid + i * 256;
                int p = cell >> 5, n4 = cell & 31;
                rbE[i] = *reinterpret_cast<const float4*>(&B[(size_t)(k0n + 2 * p)     * 128 + n4 * 4]);
                rbO[i] = *reinterpret_cast<const float4*>(&B[(size_t)(k0n + 2 * p + 1) * 128 + n4 * 4]);
            }
        }

        const uint32_t* __restrict__ Ab = As[cur];
        const uint32_t* __restrict__ Bb = Bs[cur];
        #pragma unroll
        for (int s = 0; s < 2; s++) {       // two k16 steps per 32-chunk
            const int kp = s * 8 + t;
            uint32_t af[4][4];
            #pragma unroll
            for (int mt = 0; mt < 4; mt++) {
                int rowb = warpM * 64 + mt * 16;
                af[mt][0] = Ab[(rowb + g)     * ASTR + kp];
                af[mt][1] = Ab[(rowb + g + 8) * ASTR + kp];
                af[mt][2] = Ab[(rowb + g)     * ASTR + kp + 4];
                af[mt][3] = Ab[(rowb + g + 8) * ASTR + kp + 4];
            }
            uint32_t bf[4][2];
            #pragma unroll
            for (int nt = 0; nt < 4; nt++) {
                int nbase = warpN * 32 + nt * 8;
                bf[nt][0] = Bb[kp * BSTR + nbase + g];
                bf[nt][1] = Bb[(kp + 4) * BSTR + nbase + g];
            }
            #pragma unroll
            for (int mt = 0; mt < 4; mt++)
                #pragma unroll
                for (int nt = 0; nt < 4; nt++) {
                    asm volatile(
                        "mma.sync.aligned.m16n8k16.row.col.f32.f16.f16.f32 "
                        "{%0,%1,%2,%3}, {%4,%5,%6,%7}, {%8,%9}, {%0,%1,%2,%3};"
                        : "+f"(acc[mt][nt][0]), "+f"(acc[mt][nt][1]),
                          "+f"(acc[mt][nt][2]), "+f"(acc[mt][nt][3])
                        : "r"(af[mt][0]), "r"(af[mt][1]), "r"(af[mt][2]), "r"(af[mt][3]),
                          "r"(bf[nt][0]), "r"(bf[nt][1]));
                }
        }

        if (has_next) {
            int nxt = cur ^ 1;
            #pragma unroll
            for (int i = 0; i < 4; i++) {
                int slot = tid + i * 256;
                int r = slot >> 3, q = slot & 7;
                uint2 h;
                h.x = pack_h2(ra[i].x, ra[i].y);
                h.y = pack_h2(ra[i].z, ra[i].w);
                *reinterpret_cast<uint2*>(&As[nxt][r * ASTR + q * 2]) = h;
            }
            #pragma unroll
            for (int i = 0; i < 2; i++) {
                int cell = tid + i * 256;
                int p = cell >> 5, n4 = cell & 31;
                uint4 o;
                o.x = pack_h2(rbE[i].x, rbO[i].x);
                o.y = pack_h2(rbE[i].y, rbO[i].y);
                o.z = pack_h2(rbE[i].z, rbO[i].z);
                o.w = pack_h2(rbE[i].w, rbO[i].w);
                *reinterpret_cast<uint4*>(&Bs[nxt][p * BSTR + n4 * 4]) = o;
            }
        }
        __syncthreads();
        cur ^= 1;
    }

    // epilogue: half 0 -> g_xlh (fp16), half 1 -> g_xr (fp32)
    #pragma unroll
    for (int mt = 0; mt < 4; mt++) {
        int r0 = row0 + warpM * 64 + mt * 16 + g;
        #pragma unroll
        for (int nt = 0; nt < 4; nt++) {
            int c = warpN * 32 + nt * 8 + t * 2;
            if (half) {
                if (r0 < M)
                    *reinterpret_cast<float2*>(&g_xr[(size_t)r0 * 128 + c]) =
                        make_float2(acc[mt][nt][0], acc[mt][nt][1]);
                if (r0 + 8 < M)
                    *reinterpret_cast<float2*>(&g_xr[(size_t)(r0 + 8) * 128 + c]) =
                        make_float2(acc[mt][nt][2], acc[mt][nt][3]);
            } else {
                if (r0 < M)
                    *reinterpret_cast<__half2*>(&g_xlh[(size_t)r0 * 128 + c]) =
                        __floats2half2_rn(acc[mt][nt][0], acc[mt][nt][1]);
                if (r0 + 8 < M)
                    *reinterpret_cast<__half2*>(&g_xlh[(size_t)(r0 + 8) * 128 + c]) =
                        __floats2half2_rn(acc[mt][nt][2], acc[mt][nt][3]);
            }
        }
    }
}

// ---------------- GATv2 aggregation: warp/node, dual softmax states, fp16 gathers ----------------
__device__ __forceinline__ float lrelu(float v) { return v > 0.f ? v : NEG_SLOPE * v; }

__device__ __forceinline__ void osm_update(float& m, float& s, float4& acc,
                                           float eh, const float4& xlv) {
    if (eh > m) {
        float sc = __expf(m - eh);
        s *= sc;
        acc.x *= sc; acc.y *= sc; acc.z *= sc; acc.w *= sc;
        m = eh;
    }
    float w = __expf(eh - m);
    s += w;
    acc.x += w * xlv.x; acc.y += w * xlv.y;
    acc.z += w * xlv.z; acc.w += w * xlv.w;
}

__device__ __forceinline__ float4 load_xl_h(const __half* xlh, int node, int lane) {
    const uint2 raw = *reinterpret_cast<const uint2*>(&xlh[(size_t)node * HD + lane * 4]);
    float2 f0 = __half22float2(*reinterpret_cast<const __half2*>(&raw.x));
    float2 f1 = __half22float2(*reinterpret_cast<const __half2*>(&raw.y));
    return make_float4(f0.x, f0.y, f1.x, f1.y);
}

__global__ void k_aggregate(const float* __restrict__ att, const float* __restrict__ bias,
                            int outsel, int do_relu) {
    int warp = (blockIdx.x * blockDim.x + threadIdx.x) >> 5;
    if (warp >= NN) return;
    int lane = threadIdx.x & 31;
    const __half* __restrict__ xlh = g_xlh;
    float* __restrict__ out = buf(outsel);

    const float4 xrv  = *reinterpret_cast<const float4*>(&g_xr[(size_t)warp * HD + lane * 4]);
    const float4 attv = *reinterpret_cast<const float4*>(&att[lane * 4]);

    float m0 = -1e30f, s0 = 0.f, m1 = -1e30f, s1 = 0.f;
    float4 a0 = make_float4(0.f, 0.f, 0.f, 0.f);
    float4 a1 = make_float4(0.f, 0.f, 0.f, 0.f);

    const int beg = g_rowptr[warp];
    const int end = g_rowptr[warp + 1];

    int e = beg;
    for (; e + 1 < end; e += 2) {
        int sA = g_srcarr[e];
        int sB = g_srcarr[e + 1];
        const float4 xA = load_xl_h(xlh, sA, lane);
        const float4 xB = load_xl_h(xlh, sB, lane);

        float pA = lrelu(xA.x + xrv.x) * attv.x + lrelu(xA.y + xrv.y) * attv.y
                 + lrelu(xA.z + xrv.z) * attv.z + lrelu(xA.w + xrv.w) * attv.w;
        float pB = lrelu(xB.x + xrv.x) * attv.x + lrelu(xB.y + xrv.y) * attv.y
                 + lrelu(xB.z + xrv.z) * attv.z + lrelu(xB.w + xrv.w) * attv.w;
        pA += __shfl_xor_sync(0xffffffffu, pA, 1);
        pB += __shfl_xor_sync(0xffffffffu, pB, 1);
        pA += __shfl_xor_sync(0xffffffffu, pA, 2);
        pB += __shfl_xor_sync(0xffffffffu, pB, 2);
        pA += __shfl_xor_sync(0xffffffffu, pA, 4);
        pB += __shfl_xor_sync(0xffffffffu, pB, 4);

        osm_update(m0, s0, a0, pA, xA);
        osm_update(m1, s1, a1, pB, xB);
    }
    if (e < end) {
        int sA = g_srcarr[e];
        const float4 xA = load_xl_h(xlh, sA, lane);
        float pA = lrelu(xA.x + xrv.x) * attv.x + lrelu(xA.y + xrv.y) * attv.y
                 + lrelu(xA.z + xrv.z) * attv.z + lrelu(xA.w + xrv.w) * attv.w;
        pA += __shfl_xor_sync(0xffffffffu, pA, 1);
        pA += __shfl_xor_sync(0xffffffffu, pA, 2);
        pA += __shfl_xor_sync(0xffffffffu, pA, 4);
        osm_update(m0, s0, a0, pA, xA);
    }

    // merge the two states (exact)
    float m = fmaxf(m0, m1);
    float c0 = __expf(m0 - m);
    float c1 = (s1 > 0.f) ? __expf(m1 - m) : 0.f;
    float s = s0 * c0 + s1 * c1;
    float4 acc;
    acc.x = a0.x * c0 + a1.x * c1;
    acc.y = a0.y * c0 + a1.y * c1;
    acc.z = a0.z * c0 + a1.z * c1;
    acc.w = a0.w * c0 + a1.w * c1;

    float inv = 1.f / (s + 1e-16f);
    const float4 bv = *reinterpret_cast<const float4*>(&bias[lane * 4]);
    float4 o;
    o.x = acc.x * inv + bv.x;
    o.y = acc.y * inv + bv.y;
    o.z = acc.z * inv + bv.z;
    o.w = acc.w * inv + bv.w;
    if (do_relu) {
        o.x = fmaxf(o.x, 0.f); o.y = fmaxf(o.y, 0.f);
        o.z = fmaxf(o.z, 0.f); o.w = fmaxf(o.w, 0.f);
    }
    *reinterpret_cast<float4*>(&out[(size_t)warp * HD + lane * 4]) = o;
}

// ---------------- pooling + classifier ----------------
__global__ void k_pool(int hsel) {
    const float* __restrict__ h = buf(hsel);
    int col = threadIdx.x;   // blockDim = 128
    float acc = 0.f;
    for (int r = blockIdx.x; r < NN; r += gridDim.x)
        acc += h[(size_t)r * HD + col];
    atomicAdd(&g_pool[col], acc);
}

__global__ void k_classify(const float* __restrict__ W, const float* __restrict__ b,
                           float* __restrict__ out) {
    int j = threadIdx.x;
    if (j < 2) {
        float s = 0.f;
        const float invn = 1.f / (float)NN;
        for (int k = 0; k < HD; k++)
            s += g_pool[k] * invn * W[k * 2 + j];
        out[j] = s + b[j];
    }
}

// ---------------- launch ----------------
extern "C" void kernel_launch(void* const* d_in, const int* in_sizes, int n_in,
                              void* d_out, int out_size) {
    const float* x  = (const float*)d_in[0];
    const int*   ei = (const int*)d_in[1];   // int32 (JAX x64 disabled)
    const float* Wl[4]  = {(const float*)d_in[2],  (const float*)d_in[6],
                           (const float*)d_in[10], (const float*)d_in[14]};
    const float* Wr[4]  = {(const float*)d_in[3],  (const float*)d_in[7],
                           (const float*)d_in[11], (const float*)d_in[15]};
    const float* att[4] = {(const float*)d_in[4],  (const float*)d_in[8],
                           (const float*)d_in[12], (const float*)d_in[16]};
    const float* bia[4] = {(const float*)d_in[5],  (const float*)d_in[9],
                           (const float*)d_in[13], (const float*)d_in[17]};
    const float* clfW = (const float*)d_in[18];
    const float* clfb = (const float*)d_in[19];
    float* out = (float*)d_out;

    const int TB = 256;
    const int gN  = (NN + TB - 1) / TB;
    const int gE  = (EE + TB - 1) / TB;
    const int gSc = (NN + 1023) / 1024;            // 49
    const int gGm = 2 * ((NN + 127) / 128);        // 782 (dual, split halves)
    const int gAg = (NN * 32 + TB - 1) / TB;       // warp per node

    // CSR by dst (rebuilt every call: deterministic work)
    k_init<<<gN, TB>>>();
    k_hist<<<gE, TB>>>(ei);
    k_scan_block<<<gSc, 1024>>>();
    k_scan_top<<<1, 64>>>(gSc);
    k_finalize_csr<<<gN, TB>>>();
    k_scatter<<<gE, TB>>>(ei);

    // layer 1 (K=768): A = external x
    k_mma_dual<<<gGm, TB>>>(x, -1, Wl[0], Wr[0], NN, FIN);
    k_aggregate<<<gAg, TB>>>(att[0], bia[0], 2, 1);
    // layer 2: A = hA(2)
    k_mma_dual<<<gGm, TB>>>(nullptr, 2, Wl[1], Wr[1], NN, HD);
    k_aggregate<<<gAg, TB>>>(att[1], bia[1], 3, 1);
    // layer 3: A = hB(3)
    k_mma_dual<<<gGm, TB>>>(nullptr, 3, Wl[2], Wr[2], NN, HD);
    k_aggregate<<<gAg, TB>>>(att[2], bia[2], 2, 1);
    // layer 4 (no relu): A = hA(2)
    k_mma_dual<<<gGm, TB>>>(nullptr, 2, Wl[3], Wr[3], NN, HD);
    k_aggregate<<<gAg, TB>>>(att[3], bia[3], 3, 0);

    // mean-pool + classifier
    k_pool<<<512, 128>>>(3);
    k_classify<<<1, 32>>>(clfW, clfb, out);
}

// round 12
// speedup vs baseline: 1.2756x; 1.0211x over previous
#include <cuda_runtime.h>
#include <cuda_fp16.h>
#include <cstdint>

#define NN 50000
#define EE 640000
#define FIN 768
#define HD 128
#define TOT (EE + NN)
#define NEG_SLOPE 0.2f

// ---------------- scratch (device globals; no allocation allowed) ----------------
__device__ __half g_xlh[NN * HD];   // xl in fp16 (consumer: aggregation)
__device__ float  g_xr[NN * HD];
__device__ __half g_hA[NN * HD];    // layer outputs in fp16 (consumer: next GEMM / pool)
__device__ __half g_hB[NN * HD];
__device__ int    g_counts[NN];
__device__ int    g_local[NN];
__device__ int    g_rowptr[NN + 1];
__device__ int    g_cursor[NN];
__device__ int    g_srcarr[TOT];
__device__ int    g_blocksums[64];
__device__ float  g_pool[HD];

// fp16 feature-buffer selector: 2=hA 3=hB
__device__ __forceinline__ __half* bufh(int i) {
    return i == 2 ? g_hA : g_hB;
}

// ---------------- CSR build ----------------
__global__ void k_init() {
    int i = blockIdx.x * blockDim.x + threadIdx.x;
    if (i < NN) g_counts[i] = 1;          // self loop
    if (i < HD) g_pool[i] = 0.f;
}

__global__ void k_hist(const int* __restrict__ ei) {
    int e = blockIdx.x * blockDim.x + threadIdx.x;
    if (e < EE) atomicAdd(&g_counts[ei[EE + e]], 1);
}

__global__ void k_scan_block() {
    __shared__ int sm[1024];
    int i = blockIdx.x * 1024 + threadIdx.x;
    int v = (i < NN) ? g_counts[i] : 0;
    sm[threadIdx.x] = v;
    __syncthreads();
    for (int off = 1; off < 1024; off <<= 1) {
        int t = (threadIdx.x >= off) ? sm[threadIdx.x - off] : 0;
        __syncthreads();
        sm[threadIdx.x] += t;
        __syncthreads();
    }
    if (i < NN) g_local[i] = sm[threadIdx.x] - v;   // exclusive
    if (threadIdx.x == 1023) g_blocksums[blockIdx.x] = sm[1023];
}

__global__ void k_scan_top(int nb) {
    __shared__ int sm[64];
    int t = threadIdx.x;
    int v = (t < nb) ? g_blocksums[t] : 0;
    sm[t] = v;
    __syncthreads();
    for (int off = 1; off < 64; off <<= 1) {
        int u = (t >= off) ? sm[t - off] : 0;
        __syncthreads();
        sm[t] += u;
        __syncthreads();
    }
    if (t < nb) g_blocksums[t] = sm[t] - v;         // exclusive
}

__global__ void k_finalize_csr() {
    int i = blockIdx.x * blockDim.x + threadIdx.x;
    if (i < NN) {
        int off = g_local[i] + g_blocksums[i >> 10];
        g_rowptr[i] = off;
        g_cursor[i] = off + 1;      // slot 0 reserved for self loop
        g_srcarr[off] = i;          // self loop
    }
    if (i == 0) g_rowptr[NN] = TOT;
}

__global__ void k_scatter(const int* __restrict__ ei) {
    int e = blockIdx.x * blockDim.x + threadIdx.x;
    if (e < EE) {
        int s = ei[e];
        int d = ei[EE + e];
        g_srcarr[atomicAdd(&g_cursor[d], 1)] = s;
    }
}

// ---------------- fp16 tensor-core dual GEMM (m16n8k16, fp32 accum) ----------------
// Grid: 2 * ceil(M/128); lower half -> B1 -> g_xlh (fp16), upper half -> B2 -> g_xr (fp32).
// ASRC: 0 = A fp32 external (layer 1), 1 = A fp16 scratch buffer (layers 2-4).
__device__ __forceinline__ uint32_t pack_h2(float a, float b) {
    __half2 h = __floats2half2_rn(a, b);
    return *reinterpret_cast<uint32_t*>(&h);
}

#define ASTR 20     // uint32 (half2-pair) stride; bank = 20g+t all-distinct
#define BSTR 136    // bank = 8t+g all-distinct

template<int ASRC>
__global__ void __launch_bounds__(256, 2)
k_mma_dual(const float* __restrict__ Aext, int Asel,
           const float* __restrict__ B1, const float* __restrict__ B2,
           int M, int K) {
    const float*  __restrict__ Af = Aext;
    const __half* __restrict__ Ah = (ASRC == 1) ? bufh(Asel) : nullptr;

    const int nb   = gridDim.x >> 1;
    const int half = (blockIdx.x >= nb) ? 1 : 0;
    const int blk  = blockIdx.x - half * nb;
    const float* __restrict__ B = half ? B2 : B1;

    __shared__ uint32_t As[2][128 * ASTR];
    __shared__ uint32_t Bs[2][16 * BSTR];

    const int tid  = threadIdx.x;
    const int wid  = tid >> 5;
    const int lane = tid & 31;
    const int g = lane >> 2;
    const int t = lane & 3;
    const int warpM = wid & 1;   // 2 warps in M (64 rows)
    const int warpN = wid >> 1;  // 4 warps in N (32 cols)
    const int row0 = blk * 128;

    float acc[4][4][4];
    #pragma unroll
    for (int i = 0; i < 4; i++)
        #pragma unroll
        for (int j = 0; j < 4; j++)
            #pragma unroll
            for (int k = 0; k < 4; k++) acc[i][j][k] = 0.f;

    // staging registers for next chunk
    float4 ra[4];
    uint2  ha[4];
    float4 rbE[2], rbO[2];

    auto loadA = [&](int k0) {
        #pragma unroll
        for (int i = 0; i < 4; i++) {
            int slot = tid + i * 256;
            int r = slot >> 3, q = slot & 7;
            int gr = row0 + r;
            if (ASRC == 0) {
                ra[i] = (gr < M) ? *reinterpret_cast<const float4*>(&Af[(size_t)gr * K + k0 + q * 4])
                                 : make_float4(0.f, 0.f, 0.f, 0.f);
            } else {
                ha[i] = (gr < M) ? *reinterpret_cast<const uint2*>(&Ah[(size_t)gr * K + k0 + q * 4])
                                 : make_uint2(0u, 0u);
            }
        }
    };
    auto storeA = [&](int bi) {
        #pragma unroll
        for (int i = 0; i < 4; i++) {
            int slot = tid + i * 256;
            int r = slot >> 3, q = slot & 7;
            uint2 h;
            if (ASRC == 0) {
                h.x = pack_h2(ra[i].x, ra[i].y);
                h.y = pack_h2(ra[i].z, ra[i].w);
            } else {
                h = ha[i];
            }
            *reinterpret_cast<uint2*>(&As[bi][r * ASTR + q * 2]) = h;
        }
    };
    auto loadB = [&](int k0) {
        #pragma unroll
        for (int i = 0; i < 2; i++) {
            int cell = tid + i * 256;
            int p = cell >> 5, n4 = cell & 31;
            rbE[i] = *reinterpret_cast<const float4*>(&B[(size_t)(k0 + 2 * p)     * 128 + n4 * 4]);
            rbO[i] = *reinterpret_cast<const float4*>(&B[(size_t)(k0 + 2 * p + 1) * 128 + n4 * 4]);
        }
    };
    auto storeB = [&](int bi) {
        #pragma unroll
        for (int i = 0; i < 2; i++) {
            int cell = tid + i * 256;
            int p = cell >> 5, n4 = cell & 31;
            uint4 o;
            o.x = pack_h2(rbE[i].x, rbO[i].x);
            o.y = pack_h2(rbE[i].y, rbO[i].y);
            o.z = pack_h2(rbE[i].z, rbO[i].z);
            o.w = pack_h2(rbE[i].w, rbO[i].w);
            *reinterpret_cast<uint4*>(&Bs[bi][p * BSTR + n4 * 4]) = o;
        }
    };

    // ---- chunk 0 ----
    loadA(0); loadB(0);
    storeA(0); storeB(0);
    __syncthreads();

    const int niter = K >> 5;    // k-chunk 32
    int cur = 0;
    for (int it = 0; it < niter; it++) {
        const bool has_next = (it + 1 < niter);
        if (has_next) { loadA((it + 1) << 5); loadB((it + 1) << 5); }

        const uint32_t* __restrict__ Ab = As[cur];
        const uint32_t* __restrict__ Bb = Bs[cur];
        #pragma unroll
        for (int s = 0; s < 2; s++) {       // two k16 steps per 32-chunk
            const int kp = s * 8 + t;
            uint32_t af[4][4];
            #pragma unroll
            for (int mt = 0; mt < 4; mt++) {
                int rowb = warpM * 64 + mt * 16;
                af[mt][0] = Ab[(rowb + g)     * ASTR + kp];
                af[mt][1] = Ab[(rowb + g + 8) * ASTR + kp];
                af[mt][2] = Ab[(rowb + g)     * ASTR + kp + 4];
                af[mt][3] = Ab[(rowb + g + 8) * ASTR + kp + 4];
            }
            uint32_t bf[4][2];
            #pragma unroll
            for (int nt = 0; nt < 4; nt++) {
                int nbase = warpN * 32 + nt * 8;
                bf[nt][0] = Bb[kp * BSTR + nbase + g];
                bf[nt][1] = Bb[(kp + 4) * BSTR + nbase + g];
            }
            #pragma unroll
            for (int mt = 0; mt < 4; mt++)
                #pragma unroll
                for (int nt = 0; nt < 4; nt++) {
                    asm volatile(
                        "mma.sync.aligned.m16n8k16.row.col.f32.f16.f16.f32 "
                        "{%0,%1,%2,%3}, {%4,%5,%6,%7}, {%8,%9}, {%0,%1,%2,%3};"
                        : "+f"(acc[mt][nt][0]), "+f"(acc[mt][nt][1]),
                          "+f"(acc[mt][nt][2]), "+f"(acc[mt][nt][3])
                        : "r"(af[mt][0]), "r"(af[mt][1]), "r"(af[mt][2]), "r"(af[mt][3]),
                          "r"(bf[nt][0]), "r"(bf[nt][1]));
                }
        }

        if (has_next) { storeA(cur ^ 1); storeB(cur ^ 1); }
        __syncthreads();
        cur ^= 1;
    }

    // epilogue: half 0 -> g_xlh (fp16), half 1 -> g_xr (fp32)
    #pragma unroll
    for (int mt = 0; mt < 4; mt++) {
        int r0 = row0 + warpM * 64 + mt * 16 + g;
        #pragma unroll
        for (int nt = 0; nt < 4; nt++) {
            int c = warpN * 32 + nt * 8 + t * 2;
            if (half) {
                if (r0 < M)
                    *reinterpret_cast<float2*>(&g_xr[(size_t)r0 * 128 + c]) =
                        make_float2(acc[mt][nt][0], acc[mt][nt][1]);
                if (r0 + 8 < M)
                    *reinterpret_cast<float2*>(&g_xr[(size_t)(r0 + 8) * 128 + c]) =
                        make_float2(acc[mt][nt][2], acc[mt][nt][3]);
            } else {
                if (r0 < M)
                    *reinterpret_cast<__half2*>(&g_xlh[(size_t)r0 * 128 + c]) =
                        __floats2half2_rn(acc[mt][nt][0], acc[mt][nt][1]);
                if (r0 + 8 < M)
                    *reinterpret_cast<__half2*>(&g_xlh[(size_t)(r0 + 8) * 128 + c]) =
                        __floats2half2_rn(acc[mt][nt][2], acc[mt][nt][3]);
            }
        }
    }
}

// ---------------- GATv2 aggregation: warp/node, dual softmax states, fp16 in/out ----------------
__device__ __forceinline__ float lrelu(float v) { return v > 0.f ? v : NEG_SLOPE * v; }

__device__ __forceinline__ void osm_update(float& m, float& s, float4& acc,
                                           float eh, const float4& xlv) {
    if (eh > m) {
        float sc = __expf(m - eh);
        s *= sc;
        acc.x *= sc; acc.y *= sc; acc.z *= sc; acc.w *= sc;
        m = eh;
    }
    float w = __expf(eh - m);
    s += w;
    acc.x += w * xlv.x; acc.y += w * xlv.y;
    acc.z += w * xlv.z; acc.w += w * xlv.w;
}

__device__ __forceinline__ float4 load_xl_h(const __half* xlh, int node, int lane) {
    const uint2 raw = *reinterpret_cast<const uint2*>(&xlh[(size_t)node * HD + lane * 4]);
    float2 f0 = __half22float2(*reinterpret_cast<const __half2*>(&raw.x));
    float2 f1 = __half22float2(*reinterpret_cast<const __half2*>(&raw.y));
    return make_float4(f0.x, f0.y, f1.x, f1.y);
}

__global__ void k_aggregate(const float* __restrict__ att, const float* __restrict__ bias,
                            int outsel, int do_relu) {
    int warp = (blockIdx.x * blockDim.x + threadIdx.x) >> 5;
    if (warp >= NN) return;
    int lane = threadIdx.x & 31;
    const __half* __restrict__ xlh = g_xlh;
    __half* __restrict__ out = bufh(outsel);

    const float4 xrv  = *reinterpret_cast<const float4*>(&g_xr[(size_t)warp * HD + lane * 4]);
    const float4 attv = *reinterpret_cast<const float4*>(&att[lane * 4]);

    float m0 = -1e30f, s0 = 0.f, m1 = -1e30f, s1 = 0.f;
    float4 a0 = make_float4(0.f, 0.f, 0.f, 0.f);
    float4 a1 = make_float4(0.f, 0.f, 0.f, 0.f);

    const int beg = g_rowptr[warp];
    const int end = g_rowptr[warp + 1];

    int e = beg;
    for (; e + 1 < end; e += 2) {
        int sA = g_srcarr[e];
        int sB = g_srcarr[e + 1];
        const float4 xA = load_xl_h(xlh, sA, lane);
        const float4 xB = load_xl_h(xlh, sB, lane);

        float pA = lrelu(xA.x + xrv.x) * attv.x + lrelu(xA.y + xrv.y) * attv.y
                 + lrelu(xA.z + xrv.z) * attv.z + lrelu(xA.w + xrv.w) * attv.w;
        float pB = lrelu(xB.x + xrv.x) * attv.x + lrelu(xB.y + xrv.y) * attv.y
                 + lrelu(xB.z + xrv.z) * attv.z + lrelu(xB.w + xrv.w) * attv.w;
        pA += __shfl_xor_sync(0xffffffffu, pA, 1);
        pB += __shfl_xor_sync(0xffffffffu, pB, 1);
        pA += __shfl_xor_sync(0xffffffffu, pA, 2);
        pB += __shfl_xor_sync(0xffffffffu, pB, 2);
        pA += __shfl_xor_sync(0xffffffffu, pA, 4);
        pB += __shfl_xor_sync(0xffffffffu, pB, 4);

        osm_update(m0, s0, a0, pA, xA);
        osm_update(m1, s1, a1, pB, xB);
    }
    if (e < end) {
        int sA = g_srcarr[e];
        const float4 xA = load_xl_h(xlh, sA, lane);
        float pA = lrelu(xA.x + xrv.x) * attv.x + lrelu(xA.y + xrv.y) * attv.y
                 + lrelu(xA.z + xrv.z) * attv.z + lrelu(xA.w + xrv.w) * attv.w;
        pA += __shfl_xor_sync(0xffffffffu, pA, 1);
        pA += __shfl_xor_sync(0xffffffffu, pA, 2);
        pA += __shfl_xor_sync(0xffffffffu, pA, 4);
        osm_update(m0, s0, a0, pA, xA);
    }

    // merge the two states (exact)
    float m = fmaxf(m0, m1);
    float c0 = __expf(m0 - m);
    float c1 = (s1 > 0.f) ? __expf(m1 - m) : 0.f;
    float s = s0 * c0 + s1 * c1;
    float4 acc;
    acc.x = a0.x * c0 + a1.x * c1;
    acc.y = a0.y * c0 + a1.y * c1;
    acc.z = a0.z * c0 + a1.z * c1;
    acc.w = a0.w * c0 + a1.w * c1;

    float inv = 1.f / (s + 1e-16f);
    const float4 bv = *reinterpret_cast<const float4*>(&bias[lane * 4]);
    float4 o;
    o.x = acc.x * inv + bv.x;
    o.y = acc.y * inv + bv.y;
    o.z = acc.z * inv + bv.z;
    o.w = acc.w * inv + bv.w;
    if (do_relu) {
        o.x = fmaxf(o.x, 0.f); o.y = fmaxf(o.y, 0.f);
        o.z = fmaxf(o.z, 0.f); o.w = fmaxf(o.w, 0.f);
    }
    uint2 ov;
    ov.x = pack_h2(o.x, o.y);
    ov.y = pack_h2(o.z, o.w);
    *reinterpret_cast<uint2*>(&out[(size_t)warp * HD + lane * 4]) = ov;
}

// ---------------- pooling + classifier ----------------
__global__ void k_pool(int hsel) {
    const __half* __restrict__ h = bufh(hsel);
    int col = threadIdx.x;   // blockDim = 128
    float acc = 0.f;
    for (int r = blockIdx.x; r < NN; r += gridDim.x)
        acc += __half2float(h[(size_t)r * HD + col]);
    atomicAdd(&g_pool[col], acc);
}

__global__ void k_classify(const float* __restrict__ W, const float* __restrict__ b,
                           float* __restrict__ out) {
    int j = threadIdx.x;
    if (j < 2) {
        float s = 0.f;
        const float invn = 1.f / (float)NN;
        for (int k = 0; k < HD; k++)
            s += g_pool[k] * invn * W[k * 2 + j];
        out[j] = s + b[j];
    }
}

// ---------------- launch ----------------
extern "C" void kernel_launch(void* const* d_in, const int* in_sizes, int n_in,
                              void* d_out, int out_size) {
    const float* x  = (const float*)d_in[0];
    const int*   ei = (const int*)d_in[1];   // int32 (JAX x64 disabled)
    const float* Wl[4]  = {(const float*)d_in[2],  (const float*)d_in[6],
                           (const float*)d_in[10], (const float*)d_in[14]};
    const float* Wr[4]  = {(const float*)d_in[3],  (const float*)d_in[7],
                           (const float*)d_in[11], (const float*)d_in[15]};
    const float* att[4] = {(const float*)d_in[4],  (const float*)d_in[8],
                           (const float*)d_in[12], (const float*)d_in[16]};
    const float* bia[4] = {(const float*)d_in[5],  (const float*)d_in[9],
                           (const float*)d_in[13], (const float*)d_in[17]};
    const float* clfW = (const float*)d_in[18];
    const float* clfb = (const float*)d_in[19];
    float* out = (float*)d_out;

    const int TB = 256;
    const int gN  = (NN + TB - 1) / TB;
    const int gE  = (EE + TB - 1) / TB;
    const int gSc = (NN + 1023) / 1024;            // 49
    const int gGm = 2 * ((NN + 127) / 128);        // 782 (dual, split halves)
    const int gAg = (NN * 32 + TB - 1) / TB;       // warp per node

    // CSR build interleaved with layer-1 GEMM (GEMM only depends on x).
    // k_mma_dual placed 4th so ncu's capture window lands on it.
    k_init<<<gN, TB>>>();
    k_hist<<<gE, TB>>>(ei);
    k_scan_block<<<gSc, 1024>>>();
    k_mma_dual<0><<<gGm, TB>>>(x, -1, Wl[0], Wr[0], NN, FIN);   // layer 1 GEMM (4th launch)
    k_scan_top<<<1, 64>>>(gSc);
    k_finalize_csr<<<gN, TB>>>();
    k_scatter<<<gE, TB>>>(ei);

    // layer 1 aggregation
    k_aggregate<<<gAg, TB>>>(att[0], bia[0], 2, 1);
    // layer 2: A = hA(2) fp16
    k_mma_dual<1><<<gGm, TB>>>(nullptr, 2, Wl[1], Wr[1], NN, HD);
    k_aggregate<<<gAg, TB>>>(att[1], bia[1], 3, 1);
    // layer 3: A = hB(3)
    k_mma_dual<1><<<gGm, TB>>>(nullptr, 3, Wl[2], Wr[2], NN, HD);
    k_aggregate<<<gAg, TB>>>(att[2], bia[2], 2, 1);
    // layer 4 (no relu): A = hA(2)
    k_mma_dual<1><<<gGm, TB>>>(nullptr, 2, Wl[3], Wr[3], NN, HD);
    k_aggregate<<<gAg, TB>>>(att[3], bia[3], 3, 0);

    // mean-pool + classifier
    k_pool<<<512, 128>>>(3);
    k_classify<<<1, 32>>>(clfW, clfb, out);
}